// round 17
// baseline (speedup 1.0000x reference)
#include <cuda_runtime.h>
#include <cuda_bf16.h>
#include <cstdint>

// SoftPool_2d: x (32,128,128,64) f32, 2x2/stride-2 windows.
// Round 17: occupancy experiment. Warp-M drops 64->32 positions (af resident
// 32 regs, acc 16) so the whole live set fits 85 regs; __launch_bounds__(256,3)
// forces 3 CTAs/SM -> 24 warps (+50% latency hiding) at the cost of ~19% more
// L1 wavefronts/position (B sweep amortized over 32 not 64 positions).

#define THREADS 256

// dynamic smem (bytes)
#define OFF_B    0          // We^T bf16 SW128: 128 rows x 128B  (16384)
#define OFF_A    16384      // per-warp staging: 8 warps x 2 tiles x 2048 (32768)
#define OFF_BIAS 49152      // 128 f32
#define OFF_WR   49664      // 128 f32
#define SMEM_SZ  50176      // x3 CTAs = 150528 <= 227KB carveout

__device__ __forceinline__ float tanh_fast(float x) {
    float y; asm("tanh.approx.f32 %0, %1;" : "=f"(y) : "f"(x)); return y;
}
__device__ __forceinline__ uint32_t pkbf2(float lo, float hi) {
    __nv_bfloat162 h = __floats2bfloat162_rn(lo, hi);
    return *reinterpret_cast<uint32_t*>(&h);
}
__device__ __forceinline__ void mma16816(float* c, const uint32_t* a,
                                         uint32_t b0, uint32_t b1) {
    asm volatile(
        "mma.sync.aligned.m16n8k16.row.col.f32.bf16.bf16.f32 "
        "{%0,%1,%2,%3}, {%4,%5,%6,%7}, {%8,%9}, {%0,%1,%2,%3};"
        : "+f"(c[0]), "+f"(c[1]), "+f"(c[2]), "+f"(c[3])
        : "r"(a[0]), "r"(a[1]), "r"(a[2]), "r"(a[3]), "r"(b0), "r"(b1));
}
__device__ __forceinline__ void ldsm_x4(uint32_t* r, uint32_t addr) {
    asm volatile("ldmatrix.sync.aligned.m8n8.x4.shared.b16 {%0,%1,%2,%3}, [%4];"
                 : "=r"(r[0]), "=r"(r[1]), "=r"(r[2]), "=r"(r[3]) : "r"(addr));
}
__device__ __forceinline__ uint32_t swz(uint32_t off) {
    return off ^ ((off >> 3) & 0x70);
}

__global__ __launch_bounds__(THREADS, 3)
void softpool2d_mma_kernel(const float* __restrict__ x,
                           const float* __restrict__ We,
                           const float* __restrict__ be,
                           const float* __restrict__ Wr,
                           const float* __restrict__ br,
                           float* __restrict__ out)
{
    extern __shared__ __align__(16) unsigned char smemb[];
    float* sBias = reinterpret_cast<float*>(smemb + OFF_BIAS);
    float* sWr   = reinterpret_cast<float*>(smemb + OFF_WR);

    const int tid  = threadIdx.x;
    const int wid  = tid >> 5;
    const int lane = tid & 31;
    const int g    = lane >> 2;
    const int tq   = lane & 3;

    // Stage We^T (SW128): row j holds We[:,j] as bf16
    {
        uint8_t* bp = smemb + OFF_B;
        for (int idx = tid; idx < 64 * 128; idx += THREADS) {
            int d = idx >> 7;
            int j = idx & 127;
            *reinterpret_cast<__nv_bfloat16*>(bp + swz((uint32_t)(j * 128 + d * 2)))
                = __float2bfloat16(We[idx]);
        }
    }
    if (tid < 128) {
        sBias[tid] = be[tid];
        sWr[tid]   = Wr[tid];
    }
    __syncthreads();          // only CTA-wide barrier

    const float brv = br[0];
    const uint32_t bW = (uint32_t)__cvta_generic_to_shared(smemb + OFF_B);
    const uint32_t aW = (uint32_t)__cvta_generic_to_shared(smemb + OFF_A)
                        + wid * 4096;     // 2 x 2KB tile buffers per warp

    // CTA = one q-row (64 windows). b = cta>>6, q = cta&63.
    // Warp covers 8 windows at pw = wid*8 (2 tiles of 4 windows).
    const int cta = blockIdx.x;
    const int b   = cta >> 6;
    const int q   = cta & 63;
    const int pw  = wid * 8;
    const int row0 = b * 128 + 2 * q;

    const float* __restrict__ baseq = x + ((size_t)row0 * 128 + 2 * pw) * 64;

    const uint32_t arow = (uint32_t)((lane & 15) * 128 + (lane >> 4) * 16);
    const int quad = lane >> 3;
    const uint32_t brow = (uint32_t)(((quad >> 1) * 8 + (lane & 7)) * 128
                                     + (quad & 1) * 16);

    // Per-tile chunk addressing (fixed per thread):
    // ci = it*32 + lane; m = ci>>4; c4 = ci&15; i = m>>2; w = m&3.
    int srcoff[8];
    uint32_t stoff[8];
#pragma unroll
    for (int it = 0; it < 8; ++it) {
        int ci = it * 32 + lane;
        int m  = ci >> 4;
        int c4 = ci & 15;
        int i  = m >> 2, w = m & 3;
        srcoff[it] = (i >> 1) * 8192 + w * 128 + (i & 1) * 64 + c4 * 4;
        stoff[it]  = swz((uint32_t)(m * 128 + c4 * 8));
    }

    // --- Phase 1: stage both tiles (pipelined LDG; no af live) ---
    {
        float4 v[8], vn[8];
#pragma unroll
        for (int it = 0; it < 8; ++it)
            v[it] = *reinterpret_cast<const float4*>(baseq + srcoff[it]);
#pragma unroll
        for (int it = 0; it < 8; ++it)
            vn[it] = *reinterpret_cast<const float4*>(baseq + 512 + srcoff[it]);
#pragma unroll
        for (int it = 0; it < 8; ++it) {
            uint32_t lo = pkbf2(v[it].x, v[it].y);
            uint32_t hi = pkbf2(v[it].z, v[it].w);
            asm volatile("st.shared.v2.b32 [%0], {%1,%2};"
                         :: "r"(aW + stoff[it]), "r"(lo), "r"(hi) : "memory");
        }
#pragma unroll
        for (int it = 0; it < 8; ++it) {
            uint32_t lo = pkbf2(vn[it].x, vn[it].y);
            uint32_t hi = pkbf2(vn[it].z, vn[it].w);
            asm volatile("st.shared.v2.b32 [%0], {%1,%2};"
                         :: "r"(aW + 2048 + stoff[it]), "r"(lo), "r"(hi) : "memory");
        }
    }
    __syncwarp();

    // --- Phase 2: extract 8 af fragments (no v/vn live) ---
    uint32_t af[2][4][4];
#pragma unroll
    for (int t = 0; t < 2; ++t)
#pragma unroll
        for (int kk = 0; kk < 4; ++kk)
            ldsm_x4(af[t][kk], aW + (uint32_t)(t * 2048) + swz(arow + kk * 32));

    float lsA[2] = {0, 0}, lsB[2] = {0, 0};

    // --- Hidden sweep, 8 chunks of 16 cols; B fragments 2-deep prefetched ---
    uint32_t brr[2][4];
    ldsm_x4(brr[0], bW + swz(brow));     // (h=0, kk=0)
    int pb = 0;

#pragma unroll
    for (int h = 0; h < 8; ++h) {
        float acc[2][2][4];
#pragma unroll
        for (int t = 0; t < 2; ++t)
#pragma unroll
            for (int n = 0; n < 2; ++n)
#pragma unroll
                for (int c = 0; c < 4; ++c) acc[t][n][c] = 0.0f;

#pragma unroll
        for (int kk = 0; kk < 4; ++kk) {
            if (!(h == 7 && kk == 3)) {
                const int nh  = (kk == 3) ? h + 1 : h;
                const int nkk = (kk + 1) & 3;
                ldsm_x4(brr[pb ^ 1],
                        bW + swz((uint32_t)(nh * 2048) + brow + nkk * 32));
            }
#pragma unroll
            for (int t = 0; t < 2; ++t) {
                mma16816(acc[t][0], af[t][kk], brr[pb][0], brr[pb][1]);
                mma16816(acc[t][1], af[t][kk], brr[pb][2], brr[pb][3]);
            }
            pb ^= 1;
        }

        // Fold chunk into logit partials. Lane rows: g (lsA), g+8 (lsB).
#pragma unroll
        for (int n = 0; n < 2; ++n) {
            const int j = h * 16 + n * 8 + tq * 2;
            float2 bia = *reinterpret_cast<const float2*>(&sBias[j]);
            float2 wr2 = *reinterpret_cast<const float2*>(&sWr[j]);
#pragma unroll
            for (int t = 0; t < 2; ++t) {
                lsA[t] = fmaf(tanh_fast(acc[t][n][0] + bia.x), wr2.x, lsA[t]);
                lsA[t] = fmaf(tanh_fast(acc[t][n][1] + bia.y), wr2.y, lsA[t]);
                lsB[t] = fmaf(tanh_fast(acc[t][n][2] + bia.x), wr2.x, lsB[t]);
                lsB[t] = fmaf(tanh_fast(acc[t][n][3] + bia.y), wr2.y, lsB[t]);
            }
        }
    }

    // --- Per-tile softmax + weighted sum; x loads hoisted above gate chain ---
    const int w   = g & 3;
    const int sub = ((g >> 2) << 2) + tq;     // 0..7
#pragma unroll
    for (int t = 0; t < 2; ++t) {
        const int p = pw + t * 4 + w;
        const float* __restrict__ wb = x + ((size_t)row0 * 128 + 2 * p) * 64;

        // Issue all 8 loads first (independent of the gate computation).
        float4 xa[2], xb[2], xc[2], xd[2];
#pragma unroll
        for (int hh = 0; hh < 2; ++hh) {
            const int off = hh * 32 + sub * 4;
            xa[hh] = *reinterpret_cast<const float4*>(wb + off);
            xb[hh] = *reinterpret_cast<const float4*>(wb + 64 + off);
            xc[hh] = *reinterpret_cast<const float4*>(wb + 8192 + off);
            xd[hh] = *reinterpret_cast<const float4*>(wb + 8192 + 64 + off);
        }

        float a = lsA[t], bb = lsB[t];
        a += __shfl_xor_sync(0xFFFFFFFFu, a, 1);
        a += __shfl_xor_sync(0xFFFFFFFFu, a, 2);
        bb += __shfl_xor_sync(0xFFFFFFFFu, bb, 1);
        bb += __shfl_xor_sync(0xFFFFFFFFu, bb, 2);

        // logit in (0,1); unnormalized softmax weight e = exp(logit) in (1,e)
        const float eA = __expf(1.0f / (1.0f + __expf(-(a + brv))));
        const float eB = __expf(1.0f / (1.0f + __expf(-(bb + brv))));
        const float pA = __shfl_xor_sync(0xFFFFFFFFu, eA, 16);
        const float pB = __shfl_xor_sync(0xFFFFFFFFu, eB, 16);

        float e0, e1, e2, e3;
        if (g < 4) { e0 = eA; e2 = eB; e1 = pA; e3 = pB; }
        else       { e1 = eA; e3 = eB; e0 = pA; e2 = pB; }
        const float inv = 1.0f / (e0 + e1 + e2 + e3);
        const float g0 = e0 * inv, g1 = e1 * inv, g2 = e2 * inv, g3 = e3 * inv;

        float* __restrict__ dst = out + ((size_t)(b * 64 + q) * 64 + p) * 64;
#pragma unroll
        for (int hh = 0; hh < 2; ++hh) {
            const int off = hh * 32 + sub * 4;
            float4 o;
            o.x = g0 * xa[hh].x + g1 * xb[hh].x + g2 * xc[hh].x + g3 * xd[hh].x;
            o.y = g0 * xa[hh].y + g1 * xb[hh].y + g2 * xc[hh].y + g3 * xd[hh].y;
            o.z = g0 * xa[hh].z + g1 * xb[hh].z + g2 * xc[hh].z + g3 * xd[hh].z;
            o.w = g0 * xa[hh].w + g1 * xb[hh].w + g2 * xc[hh].w + g3 * xd[hh].w;
            *reinterpret_cast<float4*>(dst + off) = o;
        }
    }
}

extern "C" void kernel_launch(void* const* d_in, const int* in_sizes, int n_in,
                              void* d_out, int out_size)
{
    const float* x  = (const float*)d_in[0];
    const float* We = (const float*)d_in[1];
    const float* be = (const float*)d_in[2];
    const float* Wr = (const float*)d_in[3];
    const float* br = (const float*)d_in[4];
    float* out = (float*)d_out;

    cudaFuncSetAttribute(softpool2d_mma_kernel,
                         cudaFuncAttributeMaxDynamicSharedMemorySize, SMEM_SZ);
    // 131072 windows / 64 per CTA = 2048 CTAs
    softpool2d_mma_kernel<<<2048, THREADS, SMEM_SZ>>>(x, We, be, Wr, br, out);
}